// round 13
// baseline (speedup 1.0000x reference)
#include <cuda_runtime.h>
#include <cuda_bf16.h>
#include <cuda_fp16.h>
#include <cstdint>

// SimCLR NT-Xent loss — bf16 mma.sync, half-tile balanced schedule (sm_100).
// K0: normalize rows -> bf16 feats only (pos term also from bf16; error ~2e-6).
// K1: persistent CTAs (2/SM). Work unit = 128x64 half-tile of a symmetric
//     128x128 tile pair (I<=J); 4160 units. vbid = (bid%148)*2 + bid/148
//     gives each SM a contiguous unit range -> per-SM load 28-29 units
//     (was 14-16 tiles with pathological heavy-pair collisions).
//     Epilogue: e' = 2^(14.43 s - 0.43) via ex2.approx.f16x2, mask,
//     shfl-reduce, direct RED.F32 scatter of row/col sums.
// K2: loss = mean(-10*pos + 10 + log(rowsum') - 14 ln2).

#define N2 8192
#define HALF 4096
#define D 128
#define NT 64
#define NPAIRS 2080
#define NUNITS (2 * NPAIRS)
#define NSM 148
#define NBLK (2 * NSM)
#define INV_T 10.0f
#define SHIFT 10.0f
#define C_EX2 14.426950408889634f   /* 10 * log2(e) */
#define BIASC (14.0f - C_EX2)       /* exponent bias: terms *= 2^14 */
#define LN2_14 9.704060527839234f   /* 14 * ln 2 */

__device__ __align__(16) __nv_bfloat16 g_bf[N2 * D];
__device__ float g_rowsum[N2];

#define SW128(o) ((o) ^ (((o) >> 3) & 0x70))

// ---------------- SMEM layout ----------------
// A tile = 128x128 bf16 = 32KB (two 16KB atom-cols, SW128).
// B half-tile = 64 rows x 128 bf16 = 16KB (one 64-row atom layout, SW128).
#define T_A 0
#define T_B 32768             /* two bufs of 16KB at +buf*16384 */
#define SMEM_TOTAL 65536      /* x2 CTAs = 128KB/SM */

__device__ __forceinline__ uint32_t smem_u32(const void* p) {
    uint32_t a;
    asm("{ .reg .u64 t; cvta.to.shared.u64 t, %1; cvt.u32.u64 %0, t; }" : "=r"(a) : "l"(p));
    return a;
}

// swizzled byte offset inside a 128x128 bf16 tile (A)
__device__ __forceinline__ uint32_t tile_off(int r, int g) {
    uint32_t off = (uint32_t)(((r >> 3) + (g >> 3) * 16) * 1024 + (r & 7) * 128 + (g & 7) * 16);
    return SW128(off);
}
// swizzled byte offset inside a 64x128 bf16 half-tile (B)
__device__ __forceinline__ uint32_t tile_off_b(int r, int g) {
    uint32_t off = (uint32_t)(((r >> 3) + (g >> 3) * 8) * 1024 + (r & 7) * 128 + (g & 7) * 16);
    return SW128(off);
}

__device__ __forceinline__ void stage_a(const __nv_bfloat16* __restrict__ src,
                                        int rowbase, uint32_t dst, int tid) {
    const char* s = (const char*)(src + (size_t)rowbase * D);
    #pragma unroll
    for (int it = 0; it < 8; ++it) {
        int q = it * 256 + tid;           // 2048 16B chunks
        int r = q >> 4, g = q & 15;
        asm volatile("cp.async.cg.shared.global [%0], [%1], 16;"
                     :: "r"(dst + tile_off(r, g)), "l"(s + r * 256 + g * 16) : "memory");
    }
}
__device__ __forceinline__ void stage_b(const __nv_bfloat16* __restrict__ src,
                                        int rowbase, uint32_t dst, int tid) {
    const char* s = (const char*)(src + (size_t)rowbase * D);
    #pragma unroll
    for (int it = 0; it < 4; ++it) {
        int q = it * 256 + tid;           // 1024 16B chunks
        int r = q >> 4, g = q & 15;
        asm volatile("cp.async.cg.shared.global [%0], [%1], 16;"
                     :: "r"(dst + tile_off_b(r, g)), "l"(s + r * 256 + g * 16) : "memory");
    }
}

#define CP_COMMIT() asm volatile("cp.async.commit_group;" ::: "memory")
#define CP_WAIT0()  asm volatile("cp.async.wait_group 0;" ::: "memory")

#define LDSM_X4(R, A)                                                          \
    asm volatile("ldmatrix.sync.aligned.m8n8.x4.shared.b16 {%0,%1,%2,%3}, [%4];" \
        : "=r"((R)[0]), "=r"((R)[1]), "=r"((R)[2]), "=r"((R)[3]) : "r"(A))

__device__ __forceinline__ void mma16816(float* c, const uint32_t* a,
                                         uint32_t b0, uint32_t b1) {
    asm volatile("mma.sync.aligned.m16n8k16.row.col.f32.bf16.bf16.f32 "
        "{%0,%1,%2,%3}, {%4,%5,%6,%7}, {%8,%9}, {%0,%1,%2,%3};"
        : "+f"(c[0]), "+f"(c[1]), "+f"(c[2]), "+f"(c[3])
        : "r"(a[0]), "r"(a[1]), "r"(a[2]), "r"(a[3]), "r"(b0), "r"(b1));
}

__device__ __forceinline__ uint32_t ex2_h2(uint32_t x) {
    uint32_t r;
    asm("ex2.approx.f16x2 %0, %1;" : "=r"(r) : "r"(x));
    return r;
}

// ---------------------------------------------------------------- K0
__global__ void k0_normalize(const float* __restrict__ z1,
                             const float* __restrict__ z2,
                             float* __restrict__ out) {
    int w = threadIdx.x >> 5, lane = threadIdx.x & 31;
    int row = blockIdx.x * 8 + w;
    const float* src = (row < HALF) ? (z1 + (size_t)row * D)
                                    : (z2 + (size_t)(row - HALF) * D);
    float4 f = ((const float4*)src)[lane];
    float ss = f.x * f.x + f.y * f.y + f.z * f.z + f.w * f.w;
    #pragma unroll
    for (int o = 16; o; o >>= 1) ss += __shfl_xor_sync(0xffffffffu, ss, o);
    float inv = rsqrtf(fmaxf(ss, 1e-24f));
    f.x *= inv; f.y *= inv; f.z *= inv; f.w *= inv;

    __nv_bfloat162 b0 = __floats2bfloat162_rn(f.x, f.y);
    __nv_bfloat162 b1 = __floats2bfloat162_rn(f.z, f.w);
    ((uint2*)(g_bf + (size_t)row * D))[lane] =
        make_uint2(*(uint32_t*)&b0, *(uint32_t*)&b1);
    if (lane == 0) g_rowsum[row] = 0.0f;
    if (blockIdx.x == 0 && threadIdx.x == 0) out[0] = 0.0f;
}

// ---------------------------------------------------------------- K1
__device__ __forceinline__ void decode_unit(int u, int& I, int& J, int& hf) {
    hf = u & 1;
    int k = u >> 1, i = 0;
    while (k >= NT - i) { k -= NT - i; ++i; }
    I = i; J = i + k;
}

__global__ void __launch_bounds__(256, 2) k1_mma() {
    extern __shared__ char smem[];
    uint32_t sb = smem_u32(smem);
    int tid = threadIdx.x, lane = tid & 31, w = tid >> 5;
    int wy = w >> 2, wx = w & 3;     // warp tile: rows wy*64 + mt*16, cols wx*16

    // SM-paired virtual bid: blocks b and b+148 share an SM (classic LUT),
    // so give them adjacent contiguous unit ranges -> per-SM load 28/29 units.
    int vbid = (blockIdx.x % NSM) * 2 + (blockIdx.x / NSM);
    int start = (int)((long long)vbid * NUNITS / NBLK);
    int end   = (int)((long long)(vbid + 1) * NUNITS / NBLK);
    if (start >= end) return;

    int I, J, hf;
    decode_unit(start, I, J, hf);
    int buf = 0;
    stage_a(g_bf, I * 128, sb + T_A, tid);
    stage_b(g_bf, J * 128 + hf * 64, sb + T_B, tid);
    CP_COMMIT(); CP_WAIT0();
    __syncthreads();

    for (int u = start; u < end; ++u) {
        bool havenext = (u + 1 < end);
        int nI = I, nJ = J, nh = hf;
        if (havenext) decode_unit(u + 1, nI, nJ, nh);
        bool pf = havenext && (nI == I);
        if (pf) {   // prefetch next B half into other buffer, overlapped
            stage_b(g_bf, nJ * 128 + nh * 64, sb + T_B + (buf ^ 1) * 16384, tid);
            CP_COMMIT();
        }

        // ---------------- compute: 8 k16-steps, 128x64 ----------------
        float acc[4][2][4];
        #pragma unroll
        for (int mt = 0; mt < 4; ++mt)
            #pragma unroll
            for (int nt = 0; nt < 2; ++nt)
                #pragma unroll
                for (int r = 0; r < 4; ++r) acc[mt][nt][r] = 0.0f;

        int rA = lane & 15;
        int rB = ((lane >> 4) << 3) + (lane & 7);
        uint32_t Ab = sb + T_A;
        uint32_t Bb = sb + T_B + buf * 16384;
        #pragma unroll
        for (int k0 = 0; k0 < 8; ++k0) {
            int gA = k0 * 2 + (lane >> 4);
            int gB = k0 * 2 + ((lane >> 3) & 1);
            uint32_t a[4][4], b[4];
            #pragma unroll
            for (int mt = 0; mt < 4; ++mt)
                LDSM_X4(a[mt], Ab + tile_off(wy * 64 + mt * 16 + rA, gA));
            LDSM_X4(b, Bb + tile_off_b(wx * 16 + rB, gB));
            // b = {n0-7/k0-7, n0-7/k8-15, n8-15/k0-7, n8-15/k8-15}
            #pragma unroll
            for (int mt = 0; mt < 4; ++mt)
                #pragma unroll
                for (int nt = 0; nt < 2; ++nt)
                    mma16816(acc[mt][nt], a[mt], b[nt * 2], b[nt * 2 + 1]);
        }

        // I-run ends next unit: issue A(+B) reload NOW to overlap epilogue.
        bool reload = havenext && !pf;
        if (reload) {
            __syncthreads();   // all warps done with ldsm reads of A/B
            stage_a(g_bf, nI * 128, sb + T_A, tid);
            stage_b(g_bf, nJ * 128 + nh * 64, sb + T_B + buf * 16384, tid);
            CP_COMMIT();
        }

        // ---------------- epilogue ----------------
        // e' = 2^(14.43 s - 0.43) = exp(10s-10) * 2^14 (f16-safe range)
        // mask: diag (I==J) / positive-pair (J-I==32): row_loc == col_loc
        bool maskT = (I == J) || (J - I == 32);
        float rs[4][2], cs[2][2];
        #pragma unroll
        for (int i = 0; i < 4; ++i) { rs[i][0] = rs[i][1] = 0.f; }
        cs[0][0] = cs[0][1] = cs[1][0] = cs[1][1] = 0.f;
        int rl0 = wy * 64 + (lane >> 2);              // + mt*16 (+8)
        int cl0 = hf * 64 + wx * 16 + (lane & 3) * 2; // + nt*8 (+1), tile-local
        #pragma unroll
        for (int mt = 0; mt < 4; ++mt) {
            int R0 = rl0 + mt * 16, R1 = R0 + 8;
            #pragma unroll
            for (int nt = 0; nt < 2; ++nt) {
                int C0 = cl0 + nt * 8, C1 = C0 + 1;
                float* c = acc[mt][nt];
                float a0 = fmaf(c[0], C_EX2, BIASC);
                float a1 = fmaf(c[1], C_EX2, BIASC);
                float a2 = fmaf(c[2], C_EX2, BIASC);
                float a3 = fmaf(c[3], C_EX2, BIASC);
                if (maskT) {                     // -60 -> 0 in f16
                    if (R0 == C0) a0 = -60.f;
                    if (R0 == C1) a1 = -60.f;
                    if (R1 == C0) a2 = -60.f;
                    if (R1 == C1) a3 = -60.f;
                }
                __half2 h01 = __floats2half2_rn(a0, a1);
                __half2 h23 = __floats2half2_rn(a2, a3);
                uint32_t e01u = ex2_h2(*(uint32_t*)&h01);
                uint32_t e23u = ex2_h2(*(uint32_t*)&h23);
                float2 e01 = __half22float2(*(__half2*)&e01u);
                float2 e23 = __half22float2(*(__half2*)&e23u);
                rs[mt][0] += e01.x + e01.y;
                rs[mt][1] += e23.x + e23.y;
                cs[nt][0] += e01.x + e23.x;
                cs[nt][1] += e01.y + e23.y;
            }
        }
        // row sums: reduce over 4 lanes of each row-quad, RED direct
        #pragma unroll
        for (int mt = 0; mt < 4; ++mt) {
            #pragma unroll
            for (int h2 = 0; h2 < 2; ++h2) {
                float v = rs[mt][h2];
                v += __shfl_xor_sync(0xffffffffu, v, 1);
                v += __shfl_xor_sync(0xffffffffu, v, 2);
                if ((lane & 3) == 0)
                    atomicAdd(&g_rowsum[I * 128 + wy * 64 + mt * 16 + (lane >> 2) + h2 * 8], v);
            }
        }
        // col sums: reduce over the 8 lanes sharing a column set, RED direct
        if (I != J) {
            #pragma unroll
            for (int nt = 0; nt < 2; ++nt) {
                #pragma unroll
                for (int h2 = 0; h2 < 2; ++h2) {
                    float v = cs[nt][h2];
                    v += __shfl_xor_sync(0xffffffffu, v, 4);
                    v += __shfl_xor_sync(0xffffffffu, v, 8);
                    v += __shfl_xor_sync(0xffffffffu, v, 16);
                    if (lane < 4)
                        atomicAdd(&g_rowsum[J * 128 + hf * 64 + wx * 16 + nt * 8 + lane * 2 + h2], v);
                }
            }
        }

        // ---------------- advance ----------------
        if (havenext) {
            CP_WAIT0();
            __syncthreads();
            if (pf) buf ^= 1;
            I = nI; J = nJ; hf = nh;
        }
    }
}

// ---------------------------------------------------------------- K2
__global__ void k2_final(float* __restrict__ out) {
    int row = (blockIdx.x * blockDim.x + threadIdx.x) >> 5;
    int lane = threadIdx.x & 31;
    int p = (row + HALF) & (N2 - 1);
    uint2 pa = ((const uint2*)(g_bf + (size_t)row * D))[lane];
    uint2 pb = ((const uint2*)(g_bf + (size_t)p * D))[lane];
    __nv_bfloat162 ax = *(__nv_bfloat162*)&pa.x, ay = *(__nv_bfloat162*)&pa.y;
    __nv_bfloat162 bx = *(__nv_bfloat162*)&pb.x, by = *(__nv_bfloat162*)&pb.y;
    float2 fax = __bfloat1622float2(ax), fay = __bfloat1622float2(ay);
    float2 fbx = __bfloat1622float2(bx), fby = __bfloat1622float2(by);
    float dot = fax.x * fbx.x + fax.y * fbx.y + fay.x * fby.x + fay.y * fby.y;
    #pragma unroll
    for (int o = 16; o; o >>= 1) dot += __shfl_xor_sync(0xffffffffu, dot, o);

    __shared__ float bs[8];
    if (lane == 0) {
        // rowsum is biased by 2^14: subtract 14 ln2
        float lossv = (-dot * INV_T + SHIFT + logf(g_rowsum[row]) - LN2_14) * (1.0f / N2);
        bs[threadIdx.x >> 5] = lossv;
    }
    __syncthreads();
    if (threadIdx.x == 0) {
        float s = 0.0f;
        #pragma unroll
        for (int i = 0; i < 8; ++i) s += bs[i];
        atomicAdd(out, s);
    }
}

// ---------------------------------------------------------------- launch
extern "C" void kernel_launch(void* const* d_in, const int* in_sizes, int n_in,
                              void* d_out, int out_size) {
    const float* z1 = (const float*)d_in[0];
    const float* z2 = (const float*)d_in[1];
    float* out = (float*)d_out;

    cudaFuncSetAttribute(k1_mma, cudaFuncAttributeMaxDynamicSharedMemorySize, SMEM_TOTAL);

    k0_normalize<<<N2 / 8, 256>>>(z1, z2, out);
    k1_mma<<<NBLK, 256, SMEM_TOTAL>>>();
    k2_final<<<N2 / 8, 256>>>(out);
}

// round 15
// speedup vs baseline: 1.2498x; 1.2498x over previous
#include <cuda_runtime.h>
#include <cuda_bf16.h>
#include <cuda_fp16.h>
#include <cstdint>

// SimCLR NT-Xent loss — bf16 mma.sync, full 128x128 tiles, balanced schedule.
// K0: normalize rows -> bf16 feats only (pos term from bf16 too; err ~2e-6).
// K1: persistent CTAs (2/SM) over symmetric 128x128 tile pairs (I<=J).
//     vbid = (bid%148)*2 + bid/148 -> each SM owns a contiguous 14-15-tile
//     range (kills the 16-tile heavy-pair SMs of the naive mapping).
//     S = A.B^T via ldmatrix + mma.sync m16n8k16 bf16 (fp32 acc in regs).
//     Epilogue: e' = 2^(14.43 s - 0.43) via ex2.approx.f16x2, mask,
//     shfl-reduce, direct RED.F32 scatter of row/col sums.
// K2: loss = mean(-10*pos + 10 + log(rowsum') - 14 ln2).

#define N2 8192
#define HALF 4096
#define D 128
#define NT 64
#define NPAIRS 2080
#define NSM 148
#define NBLK (2 * NSM)
#define INV_T 10.0f
#define SHIFT 10.0f
#define C_EX2 14.426950408889634f   /* 10 * log2(e) */
#define BIASC (14.0f - C_EX2)       /* exponent bias: terms *= 2^14 */
#define LN2_14 9.704060527839234f   /* 14 * ln 2 */

__device__ __align__(16) __nv_bfloat16 g_bf[N2 * D];
__device__ float g_rowsum[N2];

#define SW128(o) ((o) ^ (((o) >> 3) & 0x70))

// ---------------- SMEM layout ----------------
// tile = 128 rows x 128 bf16 = 32KB, two 16KB atom-columns, SW128 swizzled.
#define T_A 0
#define T_B 32768             /* two bufs of 32KB at +buf*32768 */
#define SMEM_TOTAL 98304      /* x2 CTAs = 192KB/SM */

__device__ __forceinline__ uint32_t smem_u32(const void* p) {
    uint32_t a;
    asm("{ .reg .u64 t; cvta.to.shared.u64 t, %1; cvt.u32.u64 %0, t; }" : "=r"(a) : "l"(p));
    return a;
}

// swizzled byte offset of (row r, 16B-unit g in 0..15) inside a 128x128 bf16 tile
__device__ __forceinline__ uint32_t tile_off(int r, int g) {
    uint32_t off = (uint32_t)(((r >> 3) + (g >> 3) * 16) * 1024 + (r & 7) * 128 + (g & 7) * 16);
    return SW128(off);
}

__device__ __forceinline__ void stage_async(const __nv_bfloat16* __restrict__ src,
                                            int rowbase, uint32_t dst, int tid) {
    const char* s = (const char*)(src + (size_t)rowbase * D);
    #pragma unroll
    for (int it = 0; it < 8; ++it) {
        int q = it * 256 + tid;           // 2048 16B chunks
        int r = q >> 4, g = q & 15;
        asm volatile("cp.async.cg.shared.global [%0], [%1], 16;"
                     :: "r"(dst + tile_off(r, g)), "l"(s + r * 256 + g * 16) : "memory");
    }
}

#define CP_COMMIT() asm volatile("cp.async.commit_group;" ::: "memory")
#define CP_WAIT0()  asm volatile("cp.async.wait_group 0;" ::: "memory")

#define LDSM_X4(R, A)                                                          \
    asm volatile("ldmatrix.sync.aligned.m8n8.x4.shared.b16 {%0,%1,%2,%3}, [%4];" \
        : "=r"((R)[0]), "=r"((R)[1]), "=r"((R)[2]), "=r"((R)[3]) : "r"(A))

__device__ __forceinline__ void mma16816(float* c, const uint32_t* a,
                                         uint32_t b0, uint32_t b1) {
    asm volatile("mma.sync.aligned.m16n8k16.row.col.f32.bf16.bf16.f32 "
        "{%0,%1,%2,%3}, {%4,%5,%6,%7}, {%8,%9}, {%0,%1,%2,%3};"
        : "+f"(c[0]), "+f"(c[1]), "+f"(c[2]), "+f"(c[3])
        : "r"(a[0]), "r"(a[1]), "r"(a[2]), "r"(a[3]), "r"(b0), "r"(b1));
}

__device__ __forceinline__ uint32_t ex2_h2(uint32_t x) {
    uint32_t r;
    asm("ex2.approx.f16x2 %0, %1;" : "=r"(r) : "r"(x));
    return r;
}

// ---------------------------------------------------------------- K0
__global__ void k0_normalize(const float* __restrict__ z1,
                             const float* __restrict__ z2,
                             float* __restrict__ out) {
    int w = threadIdx.x >> 5, lane = threadIdx.x & 31;
    int row = blockIdx.x * 8 + w;
    const float* src = (row < HALF) ? (z1 + (size_t)row * D)
                                    : (z2 + (size_t)(row - HALF) * D);
    float4 f = ((const float4*)src)[lane];
    float ss = f.x * f.x + f.y * f.y + f.z * f.z + f.w * f.w;
    #pragma unroll
    for (int o = 16; o; o >>= 1) ss += __shfl_xor_sync(0xffffffffu, ss, o);
    float inv = rsqrtf(fmaxf(ss, 1e-24f));
    f.x *= inv; f.y *= inv; f.z *= inv; f.w *= inv;

    __nv_bfloat162 b0 = __floats2bfloat162_rn(f.x, f.y);
    __nv_bfloat162 b1 = __floats2bfloat162_rn(f.z, f.w);
    ((uint2*)(g_bf + (size_t)row * D))[lane] =
        make_uint2(*(uint32_t*)&b0, *(uint32_t*)&b1);
    if (lane == 0) g_rowsum[row] = 0.0f;
    if (blockIdx.x == 0 && threadIdx.x == 0) out[0] = 0.0f;
}

// ---------------------------------------------------------------- K1
__device__ __forceinline__ void decode_tile(int t, int& I, int& J) {
    int k = t, i = 0;
    while (k >= NT - i) { k -= NT - i; ++i; }
    I = i; J = i + k;
}

__global__ void __launch_bounds__(256, 2) k1_mma() {
    extern __shared__ char smem[];
    uint32_t sb = smem_u32(smem);
    int tid = threadIdx.x, lane = tid & 31, w = tid >> 5;
    int wy = w >> 2, wx = w & 3;               // warp tile: rows wy*64, cols wx*32

    // Blocks b and b+148 co-reside on one SM (classic wave-1 placement).
    // Give them ADJACENT contiguous tile ranges -> per-SM load = 14 or 15
    // tiles (naive mapping gave 4 SMs two heavy 8-tile blocks = 16 tiles).
    int vbid = (blockIdx.x % NSM) * 2 + (blockIdx.x / NSM);
    int start = (int)((long long)vbid * NPAIRS / NBLK);
    int end   = (int)((long long)(vbid + 1) * NPAIRS / NBLK);
    if (start >= end) return;

    int I, J;
    decode_tile(start, I, J);
    int buf = 0;
    stage_async(g_bf, I * 128, sb + T_A, tid);
    stage_async(g_bf, J * 128, sb + T_B, tid);
    CP_COMMIT(); CP_WAIT0();
    __syncthreads();

    for (int t = start; t < end; ++t) {
        bool havenext = (t + 1 < end);
        int nI = I, nJ = J;
        if (havenext) decode_tile(t + 1, nI, nJ);
        bool pf = havenext && (nI == I);
        if (pf) {   // prefetch next B into other buffer, overlapped with compute
            stage_async(g_bf, nJ * 128, sb + T_B + (buf ^ 1) * 32768, tid);
            CP_COMMIT();
        }

        // ---------------- compute: 8 k16-steps ----------------
        float acc[4][4][4];
        #pragma unroll
        for (int mt = 0; mt < 4; ++mt)
            #pragma unroll
            for (int nt = 0; nt < 4; ++nt)
                #pragma unroll
                for (int r = 0; r < 4; ++r) acc[mt][nt][r] = 0.0f;

        int rA = lane & 15;
        int rB = ((lane >> 4) << 3) + (lane & 7);
        uint32_t Ab = sb + T_A;
        uint32_t Bb = sb + T_B + buf * 32768;
        #pragma unroll
        for (int k0 = 0; k0 < 8; ++k0) {
            int gA = k0 * 2 + (lane >> 4);
            int gB = k0 * 2 + ((lane >> 3) & 1);
            uint32_t a[4][4], b[2][4];
            #pragma unroll
            for (int mt = 0; mt < 4; ++mt)
                LDSM_X4(a[mt], Ab + tile_off(wy * 64 + mt * 16 + rA, gA));
            #pragma unroll
            for (int np = 0; np < 2; ++np)
                LDSM_X4(b[np], Bb + tile_off(wx * 32 + np * 16 + rB, gB));
            #pragma unroll
            for (int mt = 0; mt < 4; ++mt)
                #pragma unroll
                for (int nt = 0; nt < 4; ++nt)
                    mma16816(acc[mt][nt], a[mt],
                             b[nt >> 1][(nt & 1) * 2], b[nt >> 1][(nt & 1) * 2 + 1]);
        }

        // I-run ends next iteration: issue the A(+B) reload NOW so the L2
        // fetch overlaps the epilogue (compute has finished reading A).
        bool reload = havenext && !pf;
        if (reload) {
            __syncthreads();   // all warps done with ldsm reads of A/B
            stage_async(g_bf, nI * 128, sb + T_A, tid);
            stage_async(g_bf, nJ * 128, sb + T_B + buf * 32768, tid);
            CP_COMMIT();
        }

        // ---------------- epilogue (no smem, no barriers) ----------------
        // e' = 2^(14.43 s - 0.43) = exp(10s-10) * 2^14 (f16-safe range)
        // mask: diag (I==J) and positive-pair (J-I==32) both = row_loc==col_loc
        bool maskT = (I == J) || (J - I == 32);
        float rs[4][2], cs[4][2];
        #pragma unroll
        for (int i = 0; i < 4; ++i) { rs[i][0] = rs[i][1] = cs[i][0] = cs[i][1] = 0.f; }
        int rl0 = wy * 64 + (lane >> 2);          // + mt*16 (+8)
        int cl0 = wx * 32 + (lane & 3) * 2;       // + nt*8 (+1)
        #pragma unroll
        for (int mt = 0; mt < 4; ++mt) {
            int R0 = rl0 + mt * 16, R1 = R0 + 8;
            #pragma unroll
            for (int nt = 0; nt < 4; ++nt) {
                int C0 = cl0 + nt * 8, C1 = C0 + 1;
                float* c = acc[mt][nt];
                float a0 = fmaf(c[0], C_EX2, BIASC);
                float a1 = fmaf(c[1], C_EX2, BIASC);
                float a2 = fmaf(c[2], C_EX2, BIASC);
                float a3 = fmaf(c[3], C_EX2, BIASC);
                if (maskT) {                     // -60 -> 0 in f16
                    if (R0 == C0) a0 = -60.f;
                    if (R0 == C1) a1 = -60.f;
                    if (R1 == C0) a2 = -60.f;
                    if (R1 == C1) a3 = -60.f;
                }
                __half2 h01 = __floats2half2_rn(a0, a1);
                __half2 h23 = __floats2half2_rn(a2, a3);
                uint32_t e01u = ex2_h2(*(uint32_t*)&h01);
                uint32_t e23u = ex2_h2(*(uint32_t*)&h23);
                float2 e01 = __half22float2(*(__half2*)&e01u);
                float2 e23 = __half22float2(*(__half2*)&e23u);
                rs[mt][0] += e01.x + e01.y;
                rs[mt][1] += e23.x + e23.y;
                cs[nt][0] += e01.x + e23.x;
                cs[nt][1] += e01.y + e23.y;
            }
        }
        // row sums: reduce over the 4 lanes of each row-quad, RED direct
        #pragma unroll
        for (int mt = 0; mt < 4; ++mt) {
            #pragma unroll
            for (int h2 = 0; h2 < 2; ++h2) {
                float v = rs[mt][h2];
                v += __shfl_xor_sync(0xffffffffu, v, 1);
                v += __shfl_xor_sync(0xffffffffu, v, 2);
                if ((lane & 3) == 0)
                    atomicAdd(&g_rowsum[I * 128 + wy * 64 + mt * 16 + (lane >> 2) + h2 * 8], v);
            }
        }
        // col sums: reduce over the 8 lanes sharing a column set, RED direct
        if (I != J) {
            #pragma unroll
            for (int nt = 0; nt < 4; ++nt) {
                #pragma unroll
                for (int h2 = 0; h2 < 2; ++h2) {
                    float v = cs[nt][h2];
                    v += __shfl_xor_sync(0xffffffffu, v, 4);
                    v += __shfl_xor_sync(0xffffffffu, v, 8);
                    v += __shfl_xor_sync(0xffffffffu, v, 16);
                    if (lane < 4)
                        atomicAdd(&g_rowsum[J * 128 + wx * 32 + nt * 8 + lane * 2 + h2], v);
                }
            }
        }

        // ---------------- advance ----------------
        if (havenext) {
            CP_WAIT0();
            __syncthreads();
            if (pf) buf ^= 1;
            I = nI; J = nJ;
        }
    }
}

// ---------------------------------------------------------------- K2
__global__ void k2_final(float* __restrict__ out) {
    int row = (blockIdx.x * blockDim.x + threadIdx.x) >> 5;
    int lane = threadIdx.x & 31;
    int p = (row + HALF) & (N2 - 1);
    uint2 pa = ((const uint2*)(g_bf + (size_t)row * D))[lane];
    uint2 pb = ((const uint2*)(g_bf + (size_t)p * D))[lane];
    __nv_bfloat162 ax = *(__nv_bfloat162*)&pa.x, ay = *(__nv_bfloat162*)&pa.y;
    __nv_bfloat162 bx = *(__nv_bfloat162*)&pb.x, by = *(__nv_bfloat162*)&pb.y;
    float2 fax = __bfloat1622float2(ax), fay = __bfloat1622float2(ay);
    float2 fbx = __bfloat1622float2(bx), fby = __bfloat1622float2(by);
    float dot = fax.x * fbx.x + fax.y * fbx.y + fay.x * fby.x + fay.y * fby.y;
    #pragma unroll
    for (int o = 16; o; o >>= 1) dot += __shfl_xor_sync(0xffffffffu, dot, o);

    __shared__ float bs[8];
    if (lane == 0) {
        // rowsum is biased by 2^14: subtract 14 ln2
        float lossv = (-dot * INV_T + SHIFT + logf(g_rowsum[row]) - LN2_14) * (1.0f / N2);
        bs[threadIdx.x >> 5] = lossv;
    }
    __syncthreads();
    if (threadIdx.x == 0) {
        float s = 0.0f;
        #pragma unroll
        for (int i = 0; i < 8; ++i) s += bs[i];
        atomicAdd(out, s);
    }
}

// ---------------------------------------------------------------- launch
extern "C" void kernel_launch(void* const* d_in, const int* in_sizes, int n_in,
                              void* d_out, int out_size) {
    const float* z1 = (const float*)d_in[0];
    const float* z2 = (const float*)d_in[1];
    float* out = (float*)d_out;

    cudaFuncSetAttribute(k1_mma, cudaFuncAttributeMaxDynamicSharedMemorySize, SMEM_TOTAL);

    k0_normalize<<<N2 / 8, 256>>>(z1, z2, out);
    k1_mma<<<NBLK, 256, SMEM_TOTAL>>>();
    k2_final<<<N2 / 8, 256>>>(out);
}